// round 15
// baseline (speedup 1.0000x reference)
#include <cuda_runtime.h>
#include <cuda_fp16.h>
#include <cstdint>

#define TPB   128
#define TILES 8
#define RSH   40   // A-tile row stride in halves (80B = 20 words)

__device__ __forceinline__ uint32_t h2u(__half2 v) {
    return *(uint32_t*)&v;
}
// 1-word XOR swizzle keyed on row bit3: conflict-free permuted-row STS while
// keeping fragment LDS conflict-free (key constant per LDS instr).
__device__ __forceinline__ unsigned swz(unsigned byte_addr, int row) {
    return byte_addr ^ (((unsigned)(row >> 3) & 1u) << 2);
}

__global__ __launch_bounds__(TPB, 4) void dlrm_kernel(
    const int*    __restrict__ user_id,
    const int*    __restrict__ item_id,
    const int*    __restrict__ cat_id,
    const float2* __restrict__ dense,
    const float4* __restrict__ user_t,   // [NUM_USERS, 8] as [., 2] float4
    const float4* __restrict__ item_t,
    const float4* __restrict__ cat_t,
    const float*  __restrict__ w1,       // [26,16] row-major
    const float*  __restrict__ b1,       // [16]
    const float*  __restrict__ w2,       // [16]
    const float*  __restrict__ b2,       // [1]
    float*        __restrict__ out,
    int batch)
{
    // Per-warp A tile: 32 rows x 32 f16 cols (26 real + pad), stride 80B.
    // Row permutation: sample 2p -> row p, sample 2p+1 -> row p+16.
    __shared__ __align__(16) __half sA[4][32 * RSH];

    const int tid  = threadIdx.x;
    const int lane = tid & 31;
    const int wid  = tid >> 5;
    const int c    = lane & 3;
    const int g    = lane >> 2;
    const int p    = lane >> 1;
    const int h    = lane & 1;

    char* A = (char*)sA[wid];

    // ---- one-time prologue ----
    uint32_t bf[2][2][2];
#pragma unroll
    for (int nt = 0; nt < 2; nt++)
#pragma unroll
        for (int ks = 0; ks < 2; ks++)
#pragma unroll
            for (int i = 0; i < 2; i++) {
                int k0 = 16 * ks + 2 * c + 8 * i;
                int n  = 8 * nt + g;
                float f0 = (k0     < 26) ? __ldg(w1 + k0 * 16 + n)       : 0.0f;
                float f1 = (k0 + 1 < 26) ? __ldg(w1 + (k0 + 1) * 16 + n) : 0.0f;
                bf[nt][ks][i] = h2u(__float22half2_rn(make_float2(f0, f1)));
            }
    float wv[4], bv[4];
#pragma unroll
    for (int q = 0; q < 4; q++) {
        int j = 2 * c + (q & 1) + 8 * (q >> 1);
        wv[q] = __ldg(w2 + j);
        bv[q] = __ldg(b1 + j);
    }
    const float b2v = __ldg(b2);

    {   // zero pad cols 26..31 (row = lane covers all rows)
        int r = lane;
        unsigned base = (unsigned)(r * 80 + 52);
        *(uint32_t*)(A + swz(base,     r)) = 0u;
        *(uint32_t*)(A + swz(base + 4, r)) = 0u;
        *(uint32_t*)(A + swz(base + 8, r)) = 0u;
    }

    const int warpBase0 = blockIdx.x * (TPB * TILES) + wid * 32;

    // ---- depth-2 gather pipeline ----
    float4 rbuf[2][6];
    float2 dn[2];
    auto gather = [&](int t, int slot) {
        const int tb = warpBase0 + t * TPB;
        const int ge = tb + 2 * p;
#pragma unroll
        for (int T = 0; T < 3; T++) {
            const int* __restrict__ idp =
                (T == 0) ? user_id : (T == 1) ? item_id : cat_id;
            const float4* __restrict__ tab =
                (T == 0) ? user_t : (T == 1) ? item_t : cat_t;
            int2 id2 = __ldcs((const int2*)(idp + ge));
            rbuf[slot][T * 2 + 0] = tab[(long)id2.x * 2 + h];
            rbuf[slot][T * 2 + 1] = tab[(long)id2.y * 2 + h];
        }
        dn[slot] = __ldcs(dense + tb + lane);
    };

    gather(0, 0);
    gather(1, 1);

    for (int t = 0; t < TILES; t++) {
        const int tb   = warpBase0 + t * TPB;
        const int slot = t & 1;

        // ---- stage tile t into A (f32->f16), conflict-free STS.32 ----
#pragma unroll
        for (int T = 0; T < 3; T++) {
#pragma unroll
            for (int b = 0; b < 2; b++) {
                float4 v = rbuf[slot][T * 2 + b];
                uint32_t lo2 = h2u(__float22half2_rn(make_float2(v.x, v.y)));
                uint32_t hi2 = h2u(__float22half2_rn(make_float2(v.z, v.w)));
                int row = p + 16 * b;
                unsigned base = (unsigned)(row * 80 + 16 * T + 8 * h);
                *(uint32_t*)(A + swz(base,     row)) = lo2;
                *(uint32_t*)(A + swz(base + 4, row)) = hi2;
            }
        }
        {   // dense -> cols 24,25 (sample=lane -> row p+16h)
            int row = p + 16 * h;
            unsigned base = (unsigned)(row * 80 + 48);
            *(uint32_t*)(A + swz(base, row)) =
                h2u(__float22half2_rn(make_float2(dn[slot].x, dn[slot].y)));
        }
        __syncwarp();

        // ---- refill the drained slot: tile t+2 gathers get a FULL tile of cover
        if (t + 2 < TILES) gather(t + 2, slot);

        // ---- layer 1: mma.sync m16n8k16, D[32,16] = A[32,32] @ W ----
        float d[2][2][4];
#pragma unroll
        for (int mt = 0; mt < 2; mt++)
#pragma unroll
            for (int nt = 0; nt < 2; nt++)
                d[mt][nt][0] = d[mt][nt][1] = d[mt][nt][2] = d[mt][nt][3] = 0.f;
#pragma unroll
        for (int mt = 0; mt < 2; mt++)
#pragma unroll
            for (int ks = 0; ks < 2; ks++) {
                int r0 = 16 * mt + g;
                unsigned c0 = (unsigned)(r0 * 80 + 32 * ks + 4 * c);
                unsigned c1 = (unsigned)((r0 + 8) * 80 + 32 * ks + 4 * c);
                uint32_t a0 = *(uint32_t*)(A + swz(c0,      r0));
                uint32_t a1 = *(uint32_t*)(A + swz(c1,      r0 + 8));
                uint32_t a2 = *(uint32_t*)(A + swz(c0 + 16, r0));
                uint32_t a3 = *(uint32_t*)(A + swz(c1 + 16, r0 + 8));
#pragma unroll
                for (int nt = 0; nt < 2; nt++) {
                    asm volatile(
                        "mma.sync.aligned.m16n8k16.row.col.f32.f16.f16.f32 "
                        "{%0,%1,%2,%3}, {%4,%5,%6,%7}, {%8,%9}, {%0,%1,%2,%3};"
                        : "+f"(d[mt][nt][0]), "+f"(d[mt][nt][1]),
                          "+f"(d[mt][nt][2]), "+f"(d[mt][nt][3])
                        : "r"(a0), "r"(a1), "r"(a2), "r"(a3),
                          "r"(bf[nt][ks][0]), "r"(bf[nt][ks][1]));
                }
            }

        // ---- epilogue: bias+relu+w2 partials, quad reduce, sigmoid, store ----
        float P[4];
#pragma unroll
        for (int mt = 0; mt < 2; mt++)
#pragma unroll
            for (int rr = 0; rr < 2; rr++) {
                float s = 0.f;
                s = fmaf(fmaxf(d[mt][0][2 * rr]     + bv[0], 0.f), wv[0], s);
                s = fmaf(fmaxf(d[mt][0][2 * rr + 1] + bv[1], 0.f), wv[1], s);
                s = fmaf(fmaxf(d[mt][1][2 * rr]     + bv[2], 0.f), wv[2], s);
                s = fmaf(fmaxf(d[mt][1][2 * rr + 1] + bv[3], 0.f), wv[3], s);
                P[2 * mt + rr] = s;
            }
#pragma unroll
        for (int q = 0; q < 4; q++) {
            P[q] += __shfl_xor_sync(0xFFFFFFFFu, P[q], 1);
            P[q] += __shfl_xor_sync(0xFFFFFFFFu, P[q], 2);
        }
        int rho = g + 8 * c;
        int smp = (rho < 16) ? (2 * rho) : (2 * rho - 31);
        float l = ((c == 0) ? P[0] : (c == 1) ? P[1] : (c == 2) ? P[2] : P[3])
                  + b2v;
        float e = __expf(-l);
        __stcs(out + tb + smp, __fdividef(1.0f, 1.0f + e));

        __syncwarp();   // frag LDS done before next tile's STS overwrites A
    }
}

extern "C" void kernel_launch(void* const* d_in, const int* in_sizes, int n_in,
                              void* d_out, int out_size) {
    const int*    user_id = (const int*)d_in[0];
    const int*    item_id = (const int*)d_in[1];
    const int*    cat_id  = (const int*)d_in[2];
    const float2* dense   = (const float2*)d_in[3];
    const float4* user_t  = (const float4*)d_in[4];
    const float4* item_t  = (const float4*)d_in[5];
    const float4* cat_t   = (const float4*)d_in[6];
    const float*  w1      = (const float*)d_in[7];
    const float*  b1      = (const float*)d_in[8];
    const float*  w2      = (const float*)d_in[9];
    const float*  b2      = (const float*)d_in[10];
    float*        out     = (float*)d_out;

    const int batch  = in_sizes[0];
    const int blocks = batch / (TPB * TILES);   // 4194304 / 1024 = 4096

    dlrm_kernel<<<blocks, TPB>>>(user_id, item_id, cat_id, dense,
                                 user_t, item_t, cat_t,
                                 w1, b1, w2, b2, out, batch);
}

// round 17
// speedup vs baseline: 1.8210x; 1.8210x over previous
#include <cuda_runtime.h>

#define TPB 128
#define SPT 4
#define GRID 592   // 148 SMs x 4 resident CTAs: persistent

typedef unsigned long long ull;

// w1 packed as 4-weight quads: cw1[i*4+q] = (w1[i][4q+0..1], w1[i][4q+2..3])
__constant__ ulonglong2 cw1[26 * 4];

__device__ __forceinline__ ull pack2(float lo, float hi) {
    ull r;
    asm("mov.b64 %0, {%1, %2};" : "=l"(r) : "f"(lo), "f"(hi));
    return r;
}
__device__ __forceinline__ void unpack2(ull v, float& lo, float& hi) {
    asm("mov.b64 {%0, %1}, %2;" : "=f"(lo), "=f"(hi) : "l"(v));
}
__device__ __forceinline__ ull fma2(ull a, ull b, ull c) {
    ull d;
    asm("fma.rn.f32x2 %0, %1, %2, %3;" : "=l"(d) : "l"(a), "l"(b), "l"(c));
    return d;
}
__device__ __forceinline__ float getc(float4 v, int k) {
    return (k == 0) ? v.x : (k == 1) ? v.y : (k == 2) ? v.z : v.w;
}

// Gather one table's rows for all 4 samples. Cooperative pairwise: lanes
// 2k/2k+1 each fetch one 16B half of BOTH rows of the lane pair; every 128B
// line touched by exactly one instruction. Pair ids fetched as one int2 with
// evict-streaming (zero reuse; keep out of L2's table set).
__device__ __forceinline__ void gather_T(
    int warpBase, int lane, int h,
    const int* __restrict__ idp, const float4* __restrict__ tab,
    float4 (&rA)[4], float4 (&rB)[4])
{
#pragma unroll
    for (int s = 0; s < 4; s++) {
        const int ge = warpBase + s * TPB + (lane & ~1);
        int2 id2 = __ldcs((const int2*)(idp + ge));   // LDG.64.STREAM
        rA[s] = tab[2 * (long)id2.x + h];             // tables: normal caching
        rB[s] = tab[2 * (long)id2.y + h];
    }
}

// Exchange halves within lane pairs, then FMA this table's 8 features into
// all 4 samples' accumulators. Weights loaded ONCE per i (shared by samples).
__device__ __forceinline__ void process_T(
    int T, bool odd, const float4 (&rA)[4], const float4 (&rB)[4],
    ull (&acc)[4][8])
{
    float4 lo[4], hi[4];
#pragma unroll
    for (int s = 0; s < 4; s++) {
        float4 send = odd ? rA[s] : rB[s];
        float4 own  = odd ? rB[s] : rA[s];
        float4 recv;
        recv.x = __shfl_xor_sync(0xFFFFFFFFu, send.x, 1);
        recv.y = __shfl_xor_sync(0xFFFFFFFFu, send.y, 1);
        recv.z = __shfl_xor_sync(0xFFFFFFFFu, send.z, 1);
        recv.w = __shfl_xor_sync(0xFFFFFFFFu, send.w, 1);
        lo[s] = odd ? recv : own;
        hi[s] = odd ? own  : recv;
    }
#pragma unroll
    for (int ii = 0; ii < 8; ii++) {
        const int i = T * 8 + ii;
        ulonglong2 q0 = cw1[i * 4 + 0];
        ulonglong2 q1 = cw1[i * 4 + 1];
        ulonglong2 q2 = cw1[i * 4 + 2];
        ulonglong2 q3 = cw1[i * 4 + 3];
#pragma unroll
        for (int s = 0; s < 4; s++) {
            float fv = (ii < 4) ? getc(lo[s], ii) : getc(hi[s], ii - 4);
            ull pk = pack2(fv, fv);
            acc[s][0] = fma2(pk, q0.x, acc[s][0]);
            acc[s][1] = fma2(pk, q0.y, acc[s][1]);
            acc[s][2] = fma2(pk, q1.x, acc[s][2]);
            acc[s][3] = fma2(pk, q1.y, acc[s][3]);
            acc[s][4] = fma2(pk, q2.x, acc[s][4]);
            acc[s][5] = fma2(pk, q2.y, acc[s][5]);
            acc[s][6] = fma2(pk, q3.x, acc[s][6]);
            acc[s][7] = fma2(pk, q3.y, acc[s][7]);
        }
    }
}

__global__ __launch_bounds__(TPB, 4) void dlrm_kernel(
    const int*    __restrict__ user_id,
    const int*    __restrict__ item_id,
    const int*    __restrict__ cat_id,
    const float2* __restrict__ dense,
    const float4* __restrict__ user_t,   // [NUM_USERS, 8] as [., 2] float4
    const float4* __restrict__ item_t,
    const float4* __restrict__ cat_t,
    const float*  __restrict__ b1,
    const float*  __restrict__ w2,
    const float*  __restrict__ b2,
    float*        __restrict__ out,
    int nGroups)
{
    const int lane = threadIdx.x & 31;
    const int h    = lane & 1;
    const bool odd = (h != 0);
    const int warpOff = threadIdx.x & ~31;

    // Persistent grid-stride loop over 512-sample groups.
    for (int grp = blockIdx.x; grp < nGroups; grp += GRID) {
        const int blockBase = grp * (TPB * SPT);
        const int s0 = blockBase + threadIdx.x;
        const int warpBase = blockBase + warpOff;

        // Dense first (longest load->use distance), then double-buffered
        // gathers: user(T0) and item(T1) in flight together.
        float2 dn[4];
#pragma unroll
        for (int s = 0; s < 4; s++) dn[s] = __ldcs(&dense[s0 + s * TPB]);

        float4 A0[4], B0[4], A1[4], B1[4];
        gather_T(warpBase, lane, h, user_id, user_t, A0, B0);
        gather_T(warpBase, lane, h, item_id, item_t, A1, B1);

        // acc init + dense features (dn dies here, before the liveness peak)
        ull acc[4][8];
#pragma unroll
        for (int j = 0; j < 8; j++) {
            ull b = __ldg((const ull*)b1 + j);
#pragma unroll
            for (int s = 0; s < 4; s++) acc[s][j] = b;
        }
#pragma unroll
        for (int ii = 0; ii < 2; ii++) {
            const int i = 24 + ii;
            ulonglong2 q0 = cw1[i * 4 + 0];
            ulonglong2 q1 = cw1[i * 4 + 1];
            ulonglong2 q2 = cw1[i * 4 + 2];
            ulonglong2 q3 = cw1[i * 4 + 3];
#pragma unroll
            for (int s = 0; s < 4; s++) {
                float fv = (ii == 0) ? dn[s].x : dn[s].y;
                ull pk = pack2(fv, fv);
                acc[s][0] = fma2(pk, q0.x, acc[s][0]);
                acc[s][1] = fma2(pk, q0.y, acc[s][1]);
                acc[s][2] = fma2(pk, q1.x, acc[s][2]);
                acc[s][3] = fma2(pk, q1.y, acc[s][3]);
                acc[s][4] = fma2(pk, q2.x, acc[s][4]);
                acc[s][5] = fma2(pk, q2.y, acc[s][5]);
                acc[s][6] = fma2(pk, q3.x, acc[s][6]);
                acc[s][7] = fma2(pk, q3.y, acc[s][7]);
            }
        }

        // T0 compute; reuse its buffers for cat(T2) gather, covered by T1.
        process_T(0, odd, A0, B0, acc);
        gather_T(warpBase, lane, h, cat_id, cat_t, A0, B0);
        process_T(1, odd, A1, B1, acc);
        process_T(2, odd, A0, B0, acc);

        // relu + layer 2 + sigmoid (w2/b2 uniform, L1-hot)
        const float sb2 = __ldg(b2);
#pragma unroll
        for (int s = 0; s < 4; s++) {
            float l = sb2;
#pragma unroll
            for (int j = 0; j < 8; j++) {
                float h0, h1;
                unpack2(acc[s][j], h0, h1);
                l = fmaf(fmaxf(h0, 0.0f), __ldg(w2 + 2 * j),     l);
                l = fmaf(fmaxf(h1, 0.0f), __ldg(w2 + 2 * j + 1), l);
            }
            float e = __expf(-l);
            __stcs(&out[s0 + s * TPB], __fdividef(1.0f, 1.0f + e));
        }
    }
}

extern "C" void kernel_launch(void* const* d_in, const int* in_sizes, int n_in,
                              void* d_out, int out_size) {
    const int*    user_id = (const int*)d_in[0];
    const int*    item_id = (const int*)d_in[1];
    const int*    cat_id  = (const int*)d_in[2];
    const float2* dense   = (const float2*)d_in[3];
    const float4* user_t  = (const float4*)d_in[4];
    const float4* item_t  = (const float4*)d_in[5];
    const float4* cat_t   = (const float4*)d_in[6];
    const float*  w1      = (const float*)d_in[7];
    const float*  b1      = (const float*)d_in[8];
    const float*  w2      = (const float*)d_in[9];
    const float*  b2      = (const float*)d_in[10];
    float*        out     = (float*)d_out;

    // Single graph-capturable D2D memcpy node (byte layout of cw1 == w1).
    cudaMemcpyToSymbolAsync(cw1, w1, 26 * 16 * sizeof(float), 0,
                            cudaMemcpyDeviceToDevice, 0);

    const int batch   = in_sizes[0];
    const int nGroups = batch / (TPB * SPT);   // 8192
    const int blocks  = (nGroups < GRID) ? nGroups : GRID;

    dlrm_kernel<<<blocks, TPB>>>(user_id, item_id, cat_id, dense,
                                 user_t, item_t, cat_t,
                                 b1, w2, b2, out, nGroups);
}